// round 1
// baseline (speedup 1.0000x reference)
#include <cuda_runtime.h>
#include <cuda_bf16.h>
#include <cstdint>

// Problem constants (fixed by the dataset)
#define BB   4
#define TT   512
#define KK   63
#define DD   384
#define DFF  1536
#define MM   (BB*TT)          // 2048 rows per band
#define NOUT 96               // 2*BAND_W
#define BANDW 48
#define FREQ 1016             // NUM_FREQ_CH/2

// Scratch (device globals: allocation-free per harness rules)
__device__ float g_scale[MM * KK];                      // rmsnorm scale per (m,k) row
__device__ float g_H1[(size_t)KK * MM * DFF];           // tanh(h@W0+b0), per-band row-major

// ---------------------------------------------------------------------------
// Kernel 0: RMSNorm scale per row. One warp per (m,k) row of 384 floats.
// ---------------------------------------------------------------------------
__global__ __launch_bounds__(256) void rms_scale_kernel(const float* __restrict__ x)
{
    int gt   = blockIdx.x * blockDim.x + threadIdx.x;
    int row  = gt >> 5;                 // (m*63 + k)
    int lane = gt & 31;
    if (row >= MM * KK) return;
    const float* xr = x + (size_t)row * DD;
    float s = 0.f;
    #pragma unroll
    for (int i = 0; i < 3; i++) {       // 96 float4 / 32 lanes = 3
        float4 v = *reinterpret_cast<const float4*>(&xr[(lane + i * 32) * 4]);
        s += v.x*v.x + v.y*v.y + v.z*v.z + v.w*v.w;
    }
    #pragma unroll
    for (int o = 16; o > 0; o >>= 1) s += __shfl_xor_sync(0xffffffffu, s, o);
    if (lane == 0) g_scale[row] = rsqrtf(s * (1.0f / DD) + 1e-8f);
}

// ---------------------------------------------------------------------------
// Kernel 1: per-band GEMM1 + bias + tanh.
//   H1[k] (2048x1536) = tanh( (x_norm[k] (2048x384)) @ W0[k] (384x1536) + b0[k] )
// Tiles: BM=BN=128, BK=16, 256 threads, 8x8 micro-tile.
// RMSNorm scale + gamma fused into the A-tile load.
// ---------------------------------------------------------------------------
__global__ __launch_bounds__(256) void gemm1_kernel(
    const float* __restrict__ x, const float* __restrict__ gamma,
    const float* __restrict__ W0, const float* __restrict__ b0)
{
    const int k  = blockIdx.z;
    const int mb = blockIdx.y * 128;
    const int nb = blockIdx.x * 128;

    __shared__ float As[16][132];   // [kk][row], padded
    __shared__ float Bs[16][132];   // [kk][col], padded

    const int t  = threadIdx.x;
    const int tx = t & 15;
    const int ty = t >> 4;

    float acc[8][8];
    #pragma unroll
    for (int i = 0; i < 8; i++)
        #pragma unroll
        for (int j = 0; j < 8; j++) acc[i][j] = 0.f;

    for (int d0 = 0; d0 < DD; d0 += 16) {
        // --- load A tile: 128 rows x 16 cols, apply scale*gamma, store transposed
        #pragma unroll
        for (int l = 0; l < 2; l++) {
            int i   = t + l * 256;
            int row = i >> 2;
            int seg = i & 3;
            int gm  = mb + row;
            const float4 xv = *reinterpret_cast<const float4*>(
                &x[((size_t)gm * KK + k) * DD + d0 + seg * 4]);
            const float  sv = g_scale[gm * KK + k];
            const float4 gv = *reinterpret_cast<const float4*>(
                &gamma[k * DD + d0 + seg * 4]);
            As[seg*4+0][row] = xv.x * sv * gv.x;
            As[seg*4+1][row] = xv.y * sv * gv.y;
            As[seg*4+2][row] = xv.z * sv * gv.z;
            As[seg*4+3][row] = xv.w * sv * gv.w;
        }
        // --- load B tile: 16 rows x 128 cols of W0
        #pragma unroll
        for (int l = 0; l < 2; l++) {
            int i  = t + l * 256;
            int kk = i >> 5;
            int c4 = (i & 31) * 4;
            *reinterpret_cast<float4*>(&Bs[kk][c4]) =
                *reinterpret_cast<const float4*>(
                    &W0[((size_t)k * DD + d0 + kk) * DFF + nb + c4]);
        }
        __syncthreads();

        #pragma unroll
        for (int kk = 0; kk < 16; kk++) {
            float4 a0 = *reinterpret_cast<const float4*>(&As[kk][ty * 8]);
            float4 a1 = *reinterpret_cast<const float4*>(&As[kk][ty * 8 + 4]);
            float4 c0 = *reinterpret_cast<const float4*>(&Bs[kk][tx * 8]);
            float4 c1 = *reinterpret_cast<const float4*>(&Bs[kk][tx * 8 + 4]);
            float av[8] = {a0.x,a0.y,a0.z,a0.w,a1.x,a1.y,a1.z,a1.w};
            float bv[8] = {c0.x,c0.y,c0.z,c0.w,c1.x,c1.y,c1.z,c1.w};
            #pragma unroll
            for (int i = 0; i < 8; i++)
                #pragma unroll
                for (int j = 0; j < 8; j++)
                    acc[i][j] += av[i] * bv[j];
        }
        __syncthreads();
    }

    // epilogue: bias + tanh, store to scratch
    float bias[8];
    #pragma unroll
    for (int j = 0; j < 8; j++) bias[j] = b0[k * DFF + nb + tx * 8 + j];

    #pragma unroll
    for (int i = 0; i < 8; i++) {
        int gm = mb + ty * 8 + i;
        float* orow = &g_H1[((size_t)k * MM + gm) * DFF + nb + tx * 8];
        float4 o0, o1;
        o0.x = tanhf(acc[i][0] + bias[0]);
        o0.y = tanhf(acc[i][1] + bias[1]);
        o0.z = tanhf(acc[i][2] + bias[2]);
        o0.w = tanhf(acc[i][3] + bias[3]);
        o1.x = tanhf(acc[i][4] + bias[4]);
        o1.y = tanhf(acc[i][5] + bias[5]);
        o1.z = tanhf(acc[i][6] + bias[6]);
        o1.w = tanhf(acc[i][7] + bias[7]);
        *reinterpret_cast<float4*>(orow)     = o0;
        *reinterpret_cast<float4*>(orow + 4) = o1;
    }
}

// ---------------------------------------------------------------------------
// Kernel 2: per-band GEMM2 + bias + GLU + scatter-add.
//   C (2048x96) = H1[k] @ W1[k] + b1[k];  chunk = C[:, :48] * sigmoid(C[:, 48:])
//   out[b, p&1, t, p>>1] += chunk[:, j],  p = 32k + j
// Tiles: BM=128, BN=96 (full), BK=16, 256 threads; each thread: 8 rows x 3 GLU pairs.
// ---------------------------------------------------------------------------
__global__ __launch_bounds__(256) void gemm2_kernel(
    const float* __restrict__ W1, const float* __restrict__ b1,
    float* __restrict__ out)
{
    const int k  = blockIdx.y;
    const int mb = blockIdx.x * 128;

    __shared__ float As[16][132];   // [kk][row]
    __shared__ float Bs[16][96];    // [kk][col]

    const int t  = threadIdx.x;
    const int tx = t & 15;
    const int ty = t >> 4;

    float acc[8][6];
    #pragma unroll
    for (int i = 0; i < 8; i++)
        #pragma unroll
        for (int j = 0; j < 6; j++) acc[i][j] = 0.f;

    const float* H1k = &g_H1[(size_t)k * MM * DFF];

    for (int h0 = 0; h0 < DFF; h0 += 16) {
        // --- A tile: 128x16 from H1, transposed store
        #pragma unroll
        for (int l = 0; l < 2; l++) {
            int i   = t + l * 256;
            int row = i >> 2;
            int seg = i & 3;
            float4 v = *reinterpret_cast<const float4*>(
                &H1k[(size_t)(mb + row) * DFF + h0 + seg * 4]);
            As[seg*4+0][row] = v.x;
            As[seg*4+1][row] = v.y;
            As[seg*4+2][row] = v.z;
            As[seg*4+3][row] = v.w;
        }
        // --- B tile: 16x96 of W1 (384 float4, 256 threads -> 1.5 each)
        {
            int i = t;
            int row = i / 24, c4 = (i % 24) * 4;
            *reinterpret_cast<float4*>(&Bs[row][c4]) =
                *reinterpret_cast<const float4*>(
                    &W1[((size_t)k * DFF + h0 + row) * NOUT + c4]);
            i = t + 256;
            if (i < 384) {
                row = i / 24; c4 = (i % 24) * 4;
                *reinterpret_cast<float4*>(&Bs[row][c4]) =
                    *reinterpret_cast<const float4*>(
                        &W1[((size_t)k * DFF + h0 + row) * NOUT + c4]);
            }
        }
        __syncthreads();

        #pragma unroll
        for (int kk = 0; kk < 16; kk++) {
            float4 a0 = *reinterpret_cast<const float4*>(&As[kk][ty * 8]);
            float4 a1 = *reinterpret_cast<const float4*>(&As[kk][ty * 8 + 4]);
            float av[8] = {a0.x,a0.y,a0.z,a0.w,a1.x,a1.y,a1.z,a1.w};
            float bv[6];
            #pragma unroll
            for (int j = 0; j < 3; j++) {
                bv[j]     = Bs[kk][tx * 3 + j];          // 'a' half
                bv[j + 3] = Bs[kk][48 + tx * 3 + j];     // 'g' half
            }
            #pragma unroll
            for (int i = 0; i < 8; i++)
                #pragma unroll
                for (int j = 0; j < 6; j++)
                    acc[i][j] += av[i] * bv[j];
        }
        __syncthreads();
    }

    // epilogue: bias, GLU, scatter-add into (b, c, t, f)
    float ba[3], bg[3];
    #pragma unroll
    for (int j = 0; j < 3; j++) {
        ba[j] = b1[k * NOUT + tx * 3 + j];
        bg[j] = b1[k * NOUT + 48 + tx * 3 + j];
    }
    #pragma unroll
    for (int i = 0; i < 8; i++) {
        int gm = mb + ty * 8 + i;
        int bidx = gm >> 9;          // /512
        int tidx = gm & 511;
        #pragma unroll
        for (int j = 0; j < 3; j++) {
            int   jf = tx * 3 + j;                    // 0..47
            float av = acc[i][j]     + ba[j];
            float gv = acc[i][j + 3] + bg[j];
            float ch = av * (1.0f / (1.0f + __expf(-gv)));
            int   p  = k * 32 + jf;                   // freq-channel position
            int   oi = ((bidx * 2 + (p & 1)) * TT + tidx) * FREQ + (p >> 1);
            atomicAdd(&out[oi], ch);
        }
    }
}

// ---------------------------------------------------------------------------
extern "C" void kernel_launch(void* const* d_in, const int* in_sizes, int n_in,
                              void* d_out, int out_size)
{
    (void)in_sizes; (void)n_in;
    const float* x     = (const float*)d_in[0];
    const float* gamma = (const float*)d_in[1];
    const float* W0    = (const float*)d_in[2];
    const float* b0    = (const float*)d_in[3];
    const float* W1    = (const float*)d_in[4];
    const float* b1    = (const float*)d_in[5];
    float*       out   = (float*)d_out;

    // zero the overlapped-scatter output
    cudaMemsetAsync(out, 0, (size_t)out_size * sizeof(float));

    // RMSNorm scales: 129024 rows, 1 warp each
    rms_scale_kernel<<<(MM * KK * 32 + 255) / 256, 256>>>(x);

    // grouped GEMM1 + tanh
    dim3 g1(DFF / 128, MM / 128, KK);   // (12, 16, 63)
    gemm1_kernel<<<g1, 256>>>(x, gamma, W0, b0);

    // grouped GEMM2 + GLU + scatter
    dim3 g2(MM / 128, KK);              // (16, 63)
    gemm2_kernel<<<g2, 256>>>(W1, b1, out);
}

// round 4
// speedup vs baseline: 2.3197x; 2.3197x over previous
#include <cuda_runtime.h>
#include <cuda_bf16.h>
#include <cstdint>

// Problem constants
#define BB   4
#define TT   512
#define KK   63
#define DD   384
#define DFF  1536
#define MM   (BB*TT)          // 2048
#define NOUT 96
#define FREQ 1016

// ---------------------------------------------------------------------------
// Scratch (device globals; allocation-free per harness rules).
// NOTE: these are ONLY ever referenced from device code — passing a __device__
// symbol as a host-side kernel argument silently resolves to the host shadow
// address (writable via ATS on GB300!) and was the R3 zero-output bug.
// ---------------------------------------------------------------------------
__device__ __align__(16) __nv_bfloat16 g_An_hi[(size_t)KK * MM * DD];
__device__ __align__(16) __nv_bfloat16 g_An_lo[(size_t)KK * MM * DD];
__device__ __align__(16) __nv_bfloat16 g_W0T_hi[(size_t)KK * DFF * DD];
__device__ __align__(16) __nv_bfloat16 g_W0T_lo[(size_t)KK * DFF * DD];
__device__ __align__(16) __nv_bfloat16 g_W1T_hi[(size_t)KK * NOUT * DFF];
__device__ __align__(16) __nv_bfloat16 g_W1T_lo[(size_t)KK * NOUT * DFF];
__device__ __align__(16) __nv_bfloat16 g_H1h[(size_t)KK * MM * DFF];
__device__ __align__(16) __nv_bfloat16 g_H1l[(size_t)KK * MM * DFF];

// ---------------------------------------------------------------------------
// Portable PTX helpers (plain sm_103: no tcgen05 / 'a' features)
// ---------------------------------------------------------------------------
__device__ __forceinline__ uint32_t smem_u32(const void* p) {
    uint32_t a;
    asm("{ .reg .u64 t; cvta.to.shared.u64 t, %1; cvt.u32.u64 %0, t; }"
        : "=r"(a) : "l"(p));
    return a;
}
#define CP16(dst, src) \
    asm volatile("cp.async.cg.shared.global [%0], [%1], 16;" \
                 :: "r"(dst), "l"(src) : "memory")
#define CP_COMMIT() asm volatile("cp.async.commit_group;" ::: "memory")
#define CP_WAIT1()  asm volatile("cp.async.wait_group 1;"  ::: "memory")
#define CP_WAIT0()  asm volatile("cp.async.wait_group 0;"  ::: "memory")

__device__ __forceinline__ void ldsm4(uint32_t r[4], uint32_t addr) {
    asm volatile("ldmatrix.sync.aligned.m8n8.x4.shared.b16 {%0,%1,%2,%3}, [%4];"
        : "=r"(r[0]), "=r"(r[1]), "=r"(r[2]), "=r"(r[3]) : "r"(addr));
}
__device__ __forceinline__ void mma_bf16(float c[4], const uint32_t a[4],
                                         uint32_t b0, uint32_t b1) {
    asm volatile(
        "mma.sync.aligned.m16n8k16.row.col.f32.bf16.bf16.f32 "
        "{%0,%1,%2,%3}, {%4,%5,%6,%7}, {%8,%9}, {%0,%1,%2,%3};"
        : "+f"(c[0]), "+f"(c[1]), "+f"(c[2]), "+f"(c[3])
        : "r"(a[0]), "r"(a[1]), "r"(a[2]), "r"(a[3]), "r"(b0), "r"(b1));
}

// Swizzled byte offset inside a [rows x 32] bf16 tile packed as 128B lines
// (2 rows per line). Conflict-free for ldmatrix 8-row phases and cp.async.
__device__ __forceinline__ uint32_t tswz(int r, int c) {   // c: 16B chunk 0..3
    uint32_t line = (uint32_t)r >> 1;
    uint32_t pos  = ((((uint32_t)r & 1u) << 2) | (uint32_t)c) ^ (line & 7u);
    return line * 128u + pos * 16u;
}

__device__ __forceinline__ void split2(float a, float b, uint32_t& hi, uint32_t& lo) {
    __nv_bfloat16 ha = __float2bfloat16(a), hb = __float2bfloat16(b);
    float ra = a - __bfloat162float(ha);
    float rb = b - __bfloat162float(hb);
    __nv_bfloat162 H; H.x = ha; H.y = hb;
    __nv_bfloat162 L = __floats2bfloat162_rn(ra, rb);
    hi = *reinterpret_cast<uint32_t*>(&H);
    lo = *reinterpret_cast<uint32_t*>(&L);
}

// ---------------------------------------------------------------------------
// RMSNorm + gamma + bf16 hi/lo split.  x[m][k][d] -> An[k][m][d]
// ---------------------------------------------------------------------------
__global__ __launch_bounds__(256) void rms_split_kernel(
    const float* __restrict__ x, const float* __restrict__ gamma)
{
    int gt = blockIdx.x * blockDim.x + threadIdx.x;
    int row = gt >> 5, lane = gt & 31;
    if (row >= MM * KK) return;
    int m = row / KK, k = row - m * KK;

    const float* xr = x + (size_t)row * DD;
    float4 v[3];
    float s = 0.f;
    #pragma unroll
    for (int i = 0; i < 3; i++) {
        v[i] = *reinterpret_cast<const float4*>(&xr[(lane + i * 32) * 4]);
        s += v[i].x*v[i].x + v[i].y*v[i].y + v[i].z*v[i].z + v[i].w*v[i].w;
    }
    #pragma unroll
    for (int o = 16; o > 0; o >>= 1) s += __shfl_xor_sync(0xffffffffu, s, o);
    s = rsqrtf(s * (1.0f / DD) + 1e-8f);

    const float* gk = gamma + k * DD;
    __nv_bfloat16* oh = g_An_hi + ((size_t)k * MM + m) * DD;
    __nv_bfloat16* ol = g_An_lo + ((size_t)k * MM + m) * DD;
    #pragma unroll
    for (int i = 0; i < 3; i++) {
        int d = (lane + i * 32) * 4;
        float4 g = *reinterpret_cast<const float4*>(&gk[d]);
        float a0 = v[i].x*s*g.x, a1 = v[i].y*s*g.y, a2 = v[i].z*s*g.z, a3 = v[i].w*s*g.w;
        uint2 H, L;
        split2(a0, a1, H.x, L.x);
        split2(a2, a3, H.y, L.y);
        *reinterpret_cast<uint2*>(oh + d) = H;
        *reinterpret_cast<uint2*>(ol + d) = L;
    }
}

// ---------------------------------------------------------------------------
// Per-band transpose + bf16 hi/lo split.  in[k][R][C] -> dst[k][C][R]
// SEL=0 -> (g_W0T_hi, g_W0T_lo); SEL=1 -> (g_W1T_hi, g_W1T_lo).
// Destination globals resolved in DEVICE code (never passed from host).
// ---------------------------------------------------------------------------
template <int SEL>
__global__ __launch_bounds__(256) void transpose_split_kernel(
    const float* __restrict__ in, int R, int C)
{
    __nv_bfloat16* __restrict__ oh = (SEL == 0) ? g_W0T_hi : g_W1T_hi;
    __nv_bfloat16* __restrict__ ol = (SEL == 0) ? g_W0T_lo : g_W1T_lo;

    __shared__ float tile[32][33];
    const float* inp = in + (size_t)blockIdx.z * R * C;
    size_t obase = (size_t)blockIdx.z * C * R;
    int r0 = blockIdx.y * 32, c0 = blockIdx.x * 32;
    int tx = threadIdx.x, ty = threadIdx.y;

    #pragma unroll
    for (int j = 0; j < 4; j++)
        tile[ty + 8*j][tx] = inp[(size_t)(r0 + ty + 8*j) * C + c0 + tx];
    __syncthreads();
    #pragma unroll
    for (int j = 0; j < 4; j++) {
        int oc = c0 + ty + 8*j;
        float val = tile[tx][ty + 8*j];
        __nv_bfloat16 h = __float2bfloat16(val);
        float r = val - __bfloat162float(h);
        oh[obase + (size_t)oc * R + r0 + tx] = h;
        ol[obase + (size_t)oc * R + r0 + tx] = __float2bfloat16(r);
    }
}

// ---------------------------------------------------------------------------
// GEMM1 (mma.sync bf16, 3-term): H1[k] = tanh(An[k] @ W0T[k]^T + b0[k])
//   Block 128x128, K-step 32 (12 iters), cp.async double buffer.
//   8 warps as 2(M)x4(N): warp tile 64x32.
// ---------------------------------------------------------------------------
#define G1_STAGE 32768
#define G1_SMEM  (2*G1_STAGE)

__global__ __launch_bounds__(256) void gemm1_mma(const float* __restrict__ b0)
{
    extern __shared__ char smem[];
    const uint32_t sb = smem_u32(smem);
    const int t = threadIdx.x, wid = t >> 5, lane = t & 31;
    const int k = blockIdx.z, mb = blockIdx.y * 128, nb = blockIdx.x * 128;
    const int wm = wid & 1, wn = wid >> 1;

    const __nv_bfloat16* gA0 = g_An_hi  + ((size_t)k * MM  + mb) * DD;
    const __nv_bfloat16* gA1 = g_An_lo  + ((size_t)k * MM  + mb) * DD;
    const __nv_bfloat16* gB0 = g_W0T_hi + ((size_t)k * DFF + nb) * DD;
    const __nv_bfloat16* gB1 = g_W0T_lo + ((size_t)k * DFF + nb) * DD;

    const __nv_bfloat16* gbase[8];
    uint32_t sdst[8];
    #pragma unroll
    for (int j = 0; j < 8; j++) {
        int id = t + j * 256;
        int mat = id >> 9, r = (id >> 2) & 127, c = id & 3;
        const __nv_bfloat16* g =
            (mat == 0) ? gA0 : (mat == 1) ? gA1 : (mat == 2) ? gB0 : gB1;
        gbase[j] = g + (size_t)r * DD + c * 8;
        sdst[j]  = (uint32_t)(mat * 8192) + tswz(r, c);
    }

    float acc[4][4][4];
    #pragma unroll
    for (int a = 0; a < 4; a++)
        #pragma unroll
        for (int b = 0; b < 4; b++)
            #pragma unroll
            for (int c = 0; c < 4; c++) acc[a][b][c] = 0.f;

    #pragma unroll
    for (int j = 0; j < 8; j++) CP16(sb + sdst[j], gbase[j]);
    CP_COMMIT();

    for (int it = 0; it < 12; ++it) {
        if (it + 1 < 12) {
            uint32_t stn = sb + ((it + 1) & 1) * G1_STAGE;
            int k0 = (it + 1) * 32;
            #pragma unroll
            for (int j = 0; j < 8; j++) CP16(stn + sdst[j], gbase[j] + k0);
            CP_COMMIT();
            CP_WAIT1();
        } else {
            CP_WAIT0();
        }
        __syncthreads();
        const uint32_t stb = sb + (it & 1) * G1_STAGE;

        #pragma unroll
        for (int kc = 0; kc < 2; kc++) {
            const int cc = kc * 2 + (lane >> 4);
            uint32_t ah[4][4], al[4][4];
            #pragma unroll
            for (int mf = 0; mf < 4; mf++) {
                int r = wm * 64 + mf * 16 + (lane & 15);
                uint32_t so = tswz(r, cc);
                ldsm4(ah[mf], stb + so);
                ldsm4(al[mf], stb + 8192 + so);
            }
            uint32_t bh[2][4], bl[2][4];
            #pragma unroll
            for (int g = 0; g < 2; g++) {
                int r = wn * 32 + g * 16 + (lane & 15);
                uint32_t so = tswz(r, cc);
                ldsm4(bh[g], stb + 16384 + so);
                ldsm4(bl[g], stb + 24576 + so);
            }
            #pragma unroll
            for (int mf = 0; mf < 4; mf++)
                #pragma unroll
                for (int nf = 0; nf < 4; nf++) {
                    int g = nf >> 1, s = nf & 1;
                    mma_bf16(acc[mf][nf], ah[mf], bh[g][s], bh[g][s + 2]);
                    mma_bf16(acc[mf][nf], ah[mf], bl[g][s], bl[g][s + 2]);
                    mma_bf16(acc[mf][nf], al[mf], bh[g][s], bh[g][s + 2]);
                }
        }
        __syncthreads();
    }

    // epilogue: bias + tanh + bf16 split -> g_H1h/g_H1l
    const float* bb = b0 + k * DFF + nb + wn * 32;
    #pragma unroll
    for (int nf = 0; nf < 4; nf++) {
        float2 bias = *reinterpret_cast<const float2*>(&bb[nf * 8 + 2 * (lane & 3)]);
        int n = nb + wn * 32 + nf * 8 + 2 * (lane & 3);
        #pragma unroll
        for (int mf = 0; mf < 4; mf++) {
            #pragma unroll
            for (int h = 0; h < 2; h++) {
                int m = mb + wm * 64 + mf * 16 + (lane >> 2) + h * 8;
                float v0 = tanhf(acc[mf][nf][h * 2 + 0] + bias.x);
                float v1 = tanhf(acc[mf][nf][h * 2 + 1] + bias.y);
                uint32_t H, L;
                split2(v0, v1, H, L);
                size_t off = ((size_t)k * MM + m) * DFF + n;
                *reinterpret_cast<uint32_t*>(g_H1h + off) = H;
                *reinterpret_cast<uint32_t*>(g_H1l + off) = L;
            }
        }
    }
}

// ---------------------------------------------------------------------------
// GEMM2 (mma.sync bf16, 3-term): C = H1[k] @ W1T[k]^T + b1; GLU; scatter-add.
//   Block 128x96 (full N), K-step 32 (48 iters). 8 warps as 4(M)x2(N).
// ---------------------------------------------------------------------------
#define G2_STAGE 28672
#define G2_SMEM  (2*G2_STAGE)

__global__ __launch_bounds__(256) void gemm2_mma(
    const float* __restrict__ b1, float* __restrict__ out)
{
    extern __shared__ char smem[];
    const uint32_t sb = smem_u32(smem);
    const int t = threadIdx.x, wid = t >> 5, lane = t & 31;
    const int k = blockIdx.y, mb = blockIdx.x * 128;
    const int wm = wid & 3, wn = wid >> 2;

    const __nv_bfloat16* gA0 = g_H1h + ((size_t)k * MM + mb) * DFF;
    const __nv_bfloat16* gA1 = g_H1l + ((size_t)k * MM + mb) * DFF;
    const __nv_bfloat16* gB0 = g_W1T_hi + (size_t)k * NOUT * DFF;
    const __nv_bfloat16* gB1 = g_W1T_lo + (size_t)k * NOUT * DFF;

    const __nv_bfloat16* gbase[7];
    uint32_t sdst[7];
    #pragma unroll
    for (int j = 0; j < 7; j++) {
        int id = t + j * 256;
        if (id < 1024) {
            int mat = id >> 9, r = (id >> 2) & 127, c = id & 3;
            gbase[j] = ((mat == 0) ? gA0 : gA1) + (size_t)r * DFF + c * 8;
            sdst[j]  = (uint32_t)(mat * 8192) + tswz(r, c);
        } else {
            int id2 = id - 1024;
            int mat = (id2 >= 384);
            int rr = id2 - mat * 384;
            int r = rr >> 2, c = rr & 3;
            gbase[j] = ((mat == 0) ? gB0 : gB1) + (size_t)r * DFF + c * 8;
            sdst[j]  = 16384u + (uint32_t)(mat * 6144) + tswz(r, c);
        }
    }

    float acc[2][6][4];
    #pragma unroll
    for (int a = 0; a < 2; a++)
        #pragma unroll
        for (int b = 0; b < 6; b++)
            #pragma unroll
            for (int c = 0; c < 4; c++) acc[a][b][c] = 0.f;

    #pragma unroll
    for (int j = 0; j < 7; j++) CP16(sb + sdst[j], gbase[j]);
    CP_COMMIT();

    for (int it = 0; it < 48; ++it) {
        if (it + 1 < 48) {
            uint32_t stn = sb + ((it + 1) & 1) * G2_STAGE;
            int k0 = (it + 1) * 32;
            #pragma unroll
            for (int j = 0; j < 7; j++) CP16(stn + sdst[j], gbase[j] + k0);
            CP_COMMIT();
            CP_WAIT1();
        } else {
            CP_WAIT0();
        }
        __syncthreads();
        const uint32_t stb = sb + (it & 1) * G2_STAGE;

        #pragma unroll
        for (int kc = 0; kc < 2; kc++) {
            const int cc = kc * 2 + (lane >> 4);
            uint32_t ah[2][4], al[2][4];
            #pragma unroll
            for (int mf = 0; mf < 2; mf++) {
                int r = wm * 32 + mf * 16 + (lane & 15);
                uint32_t so = tswz(r, cc);
                ldsm4(ah[mf], stb + so);
                ldsm4(al[mf], stb + 8192 + so);
            }
            uint32_t bh[3][4], bl[3][4];
            #pragma unroll
            for (int g = 0; g < 3; g++) {
                int r = wn * 48 + g * 16 + (lane & 15);
                uint32_t so = tswz(r, cc);
                ldsm4(bh[g], stb + 16384 + so);
                ldsm4(bl[g], stb + 22528 + so);
            }
            #pragma unroll
            for (int mf = 0; mf < 2; mf++)
                #pragma unroll
                for (int nf = 0; nf < 6; nf++) {
                    int g = nf >> 1, s = nf & 1;
                    mma_bf16(acc[mf][nf], ah[mf], bh[g][s], bh[g][s + 2]);
                    mma_bf16(acc[mf][nf], ah[mf], bl[g][s], bl[g][s + 2]);
                    mma_bf16(acc[mf][nf], al[mf], bh[g][s], bh[g][s + 2]);
                }
        }
        __syncthreads();
    }

    // epilogue: stage C in smem, then GLU + scatter-add
    float* Cs = reinterpret_cast<float*>(smem);   // 128 x 100 floats
    #pragma unroll
    for (int nf = 0; nf < 6; nf++) {
        int n = wn * 48 + nf * 8 + 2 * (lane & 3);
        #pragma unroll
        for (int mf = 0; mf < 2; mf++) {
            #pragma unroll
            for (int h = 0; h < 2; h++) {
                int m = wm * 32 + mf * 16 + (lane >> 2) + h * 8;
                float2 v;
                v.x = acc[mf][nf][h * 2 + 0];
                v.y = acc[mf][nf][h * 2 + 1];
                *reinterpret_cast<float2*>(&Cs[m * 100 + n]) = v;
            }
        }
    }
    __syncthreads();

    {
        int m = t >> 1;
        int j0 = (t & 1) * 24;
        int gm = mb + m, bidx = gm >> 9, tidx = gm & 511;
        const float* bA = b1 + k * NOUT;
        #pragma unroll
        for (int jj = 0; jj < 24; jj++) {
            int j = j0 + jj;
            float a = Cs[m * 100 + j]      + bA[j];
            float g = Cs[m * 100 + j + 48] + bA[j + 48];
            float ch = a * (1.0f / (1.0f + __expf(-g)));
            int p = k * 32 + j;
            int oi = ((bidx * 2 + (p & 1)) * TT + tidx) * FREQ + (p >> 1);
            atomicAdd(&out[oi], ch);
        }
    }
}

// ---------------------------------------------------------------------------
extern "C" void kernel_launch(void* const* d_in, const int* in_sizes, int n_in,
                              void* d_out, int out_size)
{
    (void)in_sizes; (void)n_in;
    const float* x     = (const float*)d_in[0];
    const float* gamma = (const float*)d_in[1];
    const float* W0    = (const float*)d_in[2];
    const float* b0    = (const float*)d_in[3];
    const float* W1    = (const float*)d_in[4];
    const float* b1    = (const float*)d_in[5];
    float*       out   = (float*)d_out;

    cudaFuncSetAttribute(gemm1_mma, cudaFuncAttributeMaxDynamicSharedMemorySize, G1_SMEM);
    cudaFuncSetAttribute(gemm2_mma, cudaFuncAttributeMaxDynamicSharedMemorySize, G2_SMEM);

    cudaMemsetAsync(out, 0, (size_t)out_size * sizeof(float));

    // weight transposes + bf16 splits (destinations resolved device-side)
    {
        dim3 b(32, 8);
        dim3 g0(DFF / 32, DD / 32, KK);    // W0 [k][384][1536] -> [k][1536][384]
        transpose_split_kernel<0><<<g0, b>>>(W0, DD, DFF);
        dim3 g1(NOUT / 32, DFF / 32, KK);  // W1 [k][1536][96] -> [k][96][1536]
        transpose_split_kernel<1><<<g1, b>>>(W1, DFF, NOUT);
    }

    // RMSNorm + split
    rms_split_kernel<<<(MM * KK * 32 + 255) / 256, 256>>>(x, gamma);

    // grouped GEMM1 + tanh
    dim3 g1(DFF / 128, MM / 128, KK);      // (12, 16, 63)
    gemm1_mma<<<g1, 256, G1_SMEM>>>(b0);

    // grouped GEMM2 + GLU + scatter
    dim3 g2(MM / 128, KK);                 // (16, 63)
    gemm2_mma<<<g2, 256, G2_SMEM>>>(b1, out);
}